// round 1
// baseline (speedup 1.0000x reference)
#include <cuda_runtime.h>

// Problem constants
// x: (4, 192, 256, 256) fp32; windows 8x8, shift 4 -> 4096 windows of 192x64
// qkv_w: (576,192); dw_w: (576,1,3,3); proj_w: (192,192); temperature: (6,)

__device__ float g_qkv[4096 * 576 * 64];   // post-dwconv qkv, [win][ch 0..575][pos 0..63]
__device__ float g_att[4096 * 192 * 64];   // attention output pre-proj, [win][ch][pos]

// ---------------------------------------------------------------------------
// Kernel 1: per (window, third): C[192,64] = qkv_w[third*192.., :192] @ Xwin[192,64]
// with the (-4,-4) roll + window gather fused into the X load, and the
// per-window zero-padded depthwise 3x3 conv fused into the epilogue.
// ---------------------------------------------------------------------------
__global__ __launch_bounds__(256, 2) void k1_qkv_dw(
    const float* __restrict__ x, const float* __restrict__ qkv_w,
    const float* __restrict__ dw_w) {
  __shared__ __align__(16) float sm[12288];   // 48KB: Ws(192*17)+Xs(16*64) then Cs(192*64)
  float* Wsp = sm;          // 3264 floats
  float* Xsp = sm + 3264;   // 1024 floats

  const int tid = threadIdx.x;
  const int win = blockIdx.x, third = blockIdx.y;
  const int b = win >> 10, wy = (win >> 5) & 31, wx = win & 31;
  const int hbase = wy * 8 + 4, wbase = wx * 8 + 4;   // roll(-4): rolled (h) = x[h+4]
  const int tx = tid & 15, ty = tid >> 4;
  const int wrow0 = third * 192;

  float acc[12][4];
#pragma unroll
  for (int i = 0; i < 12; ++i)
#pragma unroll
    for (int j = 0; j < 4; ++j) acc[i][j] = 0.f;

  for (int kc = 0; kc < 192; kc += 16) {
    // Load W tile: 192 rows x 16 cols
#pragma unroll
    for (int t = 0; t < 12; ++t) {
      int idx = t * 256 + tid;
      int o = idx >> 4, cc = idx & 15;
      Wsp[o * 17 + cc] = qkv_w[(wrow0 + o) * 192 + kc + cc];
    }
    // Load X tile: 16 channels x 64 positions, gathered with roll
    {
      int cc = tid >> 4, rem = tid & 15;
      int i = rem >> 1, j0 = (rem & 1) * 4;
      int hh = (hbase + i) & 255;
      const float* xp = x + (((b * 192 + kc + cc) << 8) + hh) * 256;
#pragma unroll
      for (int jj = 0; jj < 4; ++jj) {
        int ww = (wbase + j0 + jj) & 255;
        Xsp[cc * 64 + i * 8 + j0 + jj] = xp[ww];
      }
    }
    __syncthreads();
#pragma unroll
    for (int cc = 0; cc < 16; ++cc) {
      float a[12];
#pragma unroll
      for (int i = 0; i < 12; ++i) a[i] = Wsp[(ty + 16 * i) * 17 + cc];
      float4 bv = *(const float4*)&Xsp[cc * 64 + tx * 4];
#pragma unroll
      for (int i = 0; i < 12; ++i) {
        acc[i][0] += a[i] * bv.x;
        acc[i][1] += a[i] * bv.y;
        acc[i][2] += a[i] * bv.z;
        acc[i][3] += a[i] * bv.w;
      }
    }
    __syncthreads();
  }

  // Stage pre-conv qkv tile into smem (reuses Ws/Xs region)
  float* Cs = sm;
#pragma unroll
  for (int i = 0; i < 12; ++i) {
    *(float4*)&Cs[(ty + 16 * i) * 64 + tx * 4] =
        make_float4(acc[i][0], acc[i][1], acc[i][2], acc[i][3]);
  }
  __syncthreads();

  // Depthwise 3x3, zero padding at window boundary
  const int ip = tx >> 1, j0 = (tx & 1) * 4;
  float* gout = g_qkv + (long long)win * 36864 + wrow0 * 64;
#pragma unroll
  for (int i12 = 0; i12 < 12; ++i12) {
    int o = ty + 16 * i12;
    const float* wp = dw_w + (wrow0 + o) * 9;
    float w9[9];
#pragma unroll
    for (int q = 0; q < 9; ++q) w9[q] = wp[q];
    const float* crow = Cs + o * 64;
    float res[4];
#pragma unroll
    for (int jj = 0; jj < 4; ++jj) {
      int j = j0 + jj;
      float s = 0.f;
#pragma unroll
      for (int di = 0; di < 3; ++di) {
        int ii = ip + di - 1;
        if ((unsigned)ii < 8u) {
#pragma unroll
          for (int dj = 0; dj < 3; ++dj) {
            int jc = j + dj - 1;
            if ((unsigned)jc < 8u) s += w9[di * 3 + dj] * crow[ii * 8 + jc];
          }
        }
      }
      res[jj] = s;
    }
    *(float4*)&gout[o * 64 + ip * 8 + j0] = make_float4(res[0], res[1], res[2], res[3]);
  }
}

// ---------------------------------------------------------------------------
// Kernel 2: per (window, head): L2 norms, channel attention 32x32, softmax,
// out = attn @ v. Stores to g_att.
// ---------------------------------------------------------------------------
__global__ __launch_bounds__(256) void k2_attn(const float* __restrict__ temp) {
  __shared__ __align__(16) float qs[32 * 68];
  __shared__ __align__(16) float ks[32 * 68];
  __shared__ __align__(16) float vs[32 * 68];
  __shared__ float attn[32 * 33];
  __shared__ float qsc[32], ksc[32];

  const int tid = threadIdx.x;
  const int win = blockIdx.x, head = blockIdx.y;
  const float* base = g_qkv + (long long)win * 36864 + head * 2048;

#pragma unroll
  for (int t = 0; t < 2; ++t) {
    int idx = t * 256 + tid;
    int r = idx >> 4, c4 = (idx & 15) * 4;
    *(float4*)&qs[r * 68 + c4] = *(const float4*)&base[r * 64 + c4];
    *(float4*)&ks[r * 68 + c4] = *(const float4*)&base[12288 + r * 64 + c4];
    *(float4*)&vs[r * 68 + c4] = *(const float4*)&base[24576 + r * 64 + c4];
  }
  __syncthreads();

  // Row L2 norms (8 threads per row)
  {
    int r = tid >> 3, l = tid & 7;
    const float* qr = qs + r * 68 + l * 8;
    const float* kr = ks + r * 68 + l * 8;
    float sq = 0.f, sk = 0.f;
#pragma unroll
    for (int t = 0; t < 8; ++t) { sq += qr[t] * qr[t]; sk += kr[t] * kr[t]; }
#pragma unroll
    for (int m = 1; m < 8; m <<= 1) {
      sq += __shfl_xor_sync(0xffffffffu, sq, m);
      sk += __shfl_xor_sync(0xffffffffu, sk, m);
    }
    if (l == 0) {
      qsc[r] = 1.f / fmaxf(sqrtf(sq), 1e-12f);
      ksc[r] = 1.f / fmaxf(sqrtf(sk), 1e-12f);
    }
  }
  __syncthreads();

  // attn logits: each thread 4 entries (same q row, 4 consecutive k rows)
  {
    const float tv = temp[head];
    int rr = tid >> 3;
    int cc0 = (tid & 7) * 4;
    const float* qr = qs + rr * 68;
    float d0 = 0.f, d1 = 0.f, d2 = 0.f, d3 = 0.f;
#pragma unroll
    for (int k = 0; k < 64; k += 4) {
      float4 qv = *(const float4*)(qr + k);
      float4 ka = *(const float4*)(ks + (cc0 + 0) * 68 + k);
      float4 kb = *(const float4*)(ks + (cc0 + 1) * 68 + k);
      float4 kc = *(const float4*)(ks + (cc0 + 2) * 68 + k);
      float4 kd = *(const float4*)(ks + (cc0 + 3) * 68 + k);
      d0 += qv.x * ka.x + qv.y * ka.y + qv.z * ka.z + qv.w * ka.w;
      d1 += qv.x * kb.x + qv.y * kb.y + qv.z * kb.z + qv.w * kb.w;
      d2 += qv.x * kc.x + qv.y * kc.y + qv.z * kc.z + qv.w * kc.w;
      d3 += qv.x * kd.x + qv.y * kd.y + qv.z * kd.z + qv.w * kd.w;
    }
    float qq = qsc[rr] * tv;
    attn[rr * 33 + cc0 + 0] = d0 * qq * ksc[cc0 + 0];
    attn[rr * 33 + cc0 + 1] = d1 * qq * ksc[cc0 + 1];
    attn[rr * 33 + cc0 + 2] = d2 * qq * ksc[cc0 + 2];
    attn[rr * 33 + cc0 + 3] = d3 * qq * ksc[cc0 + 3];
  }
  __syncthreads();

  // Softmax per row (warp 0, one thread per row)
  if (tid < 32) {
    float m = -1e30f;
#pragma unroll
    for (int c = 0; c < 32; ++c) m = fmaxf(m, attn[tid * 33 + c]);
    float s = 0.f;
#pragma unroll
    for (int c = 0; c < 32; ++c) {
      float e = __expf(attn[tid * 33 + c] - m);
      attn[tid * 33 + c] = e;
      s += e;
    }
    float inv = 1.f / s;
#pragma unroll
    for (int c = 0; c < 32; ++c) attn[tid * 33 + c] *= inv;
  }
  __syncthreads();

  // out = attn @ v : each thread one (row, 8 positions)
  {
    int ro = tid >> 3, p0 = (tid & 7) * 8;
    float4 o0 = make_float4(0.f, 0.f, 0.f, 0.f);
    float4 o1 = make_float4(0.f, 0.f, 0.f, 0.f);
    const float* ar = attn + ro * 33;
#pragma unroll
    for (int c = 0; c < 32; ++c) {
      float a = ar[c];
      float4 v0 = *(const float4*)(vs + c * 68 + p0);
      float4 v1 = *(const float4*)(vs + c * 68 + p0 + 4);
      o0.x += a * v0.x; o0.y += a * v0.y; o0.z += a * v0.z; o0.w += a * v0.w;
      o1.x += a * v1.x; o1.y += a * v1.y; o1.z += a * v1.z; o1.w += a * v1.w;
    }
    float* dst = g_att + (long long)win * 12288 + (head * 32 + ro) * 64 + p0;
    *(float4*)dst = o0;
    *(float4*)(dst + 4) = o1;
  }
}

// ---------------------------------------------------------------------------
// Kernel 3: per window: out[192,64] = proj_w[192,192] @ att[192,64], scattered
// to d_out with window-reverse + roll(+4,+4).
// ---------------------------------------------------------------------------
__global__ __launch_bounds__(256, 2) void k3_proj(
    const float* __restrict__ proj_w, float* __restrict__ out) {
  __shared__ __align__(16) float sm[4288];   // Ws 192*17 + Xs 16*64
  float* Wsp = sm;
  float* Xsp = sm + 3264;

  const int tid = threadIdx.x;
  const int win = blockIdx.x;
  const int b = win >> 10, wy = (win >> 5) & 31, wx = win & 31;
  const int tx = tid & 15, ty = tid >> 4;

  float acc[12][4];
#pragma unroll
  for (int i = 0; i < 12; ++i)
#pragma unroll
    for (int j = 0; j < 4; ++j) acc[i][j] = 0.f;

  const float* att = g_att + (long long)win * 12288;
  for (int kc = 0; kc < 192; kc += 16) {
#pragma unroll
    for (int t = 0; t < 12; ++t) {
      int idx = t * 256 + tid;
      int o = idx >> 4, cc = idx & 15;
      Wsp[o * 17 + cc] = proj_w[o * 192 + kc + cc];
    }
    {
      int cc = tid >> 4, p4 = (tid & 15) * 4;
      *(float4*)&Xsp[cc * 64 + p4] = *(const float4*)&att[(kc + cc) * 64 + p4];
    }
    __syncthreads();
#pragma unroll
    for (int cc = 0; cc < 16; ++cc) {
      float a[12];
#pragma unroll
      for (int i = 0; i < 12; ++i) a[i] = Wsp[(ty + 16 * i) * 17 + cc];
      float4 bv = *(const float4*)&Xsp[cc * 64 + tx * 4];
#pragma unroll
      for (int i = 0; i < 12; ++i) {
        acc[i][0] += a[i] * bv.x;
        acc[i][1] += a[i] * bv.y;
        acc[i][2] += a[i] * bv.z;
        acc[i][3] += a[i] * bv.w;
      }
    }
    __syncthreads();
  }

  // Scatter with window reverse + roll(+4,+4): final[h] = img[(h-4)%256]
  const int ip = tx >> 1, j0 = (tx & 1) * 4;
  const int hh = (wy * 8 + ip + 4) & 255;
#pragma unroll
  for (int i = 0; i < 12; ++i) {
    int o = ty + 16 * i;
    float* orow = out + (((b * 192 + o) << 8) + hh) * 256;
#pragma unroll
    for (int jj = 0; jj < 4; ++jj) {
      int ww = (wx * 8 + j0 + jj + 4) & 255;
      orow[ww] = acc[i][jj];
    }
  }
}

extern "C" void kernel_launch(void* const* d_in, const int* in_sizes, int n_in,
                              void* d_out, int out_size) {
  const float *x = nullptr, *qkvw = nullptr, *dww = nullptr, *projw = nullptr,
              *temp = nullptr;
  for (int i = 0; i < n_in; ++i) {
    switch (in_sizes[i]) {
      case 50331648: x = (const float*)d_in[i]; break;      // 4*192*256*256
      case 110592:   qkvw = (const float*)d_in[i]; break;   // 576*192
      case 5184:     dww = (const float*)d_in[i]; break;    // 576*9
      case 36864:    projw = (const float*)d_in[i]; break;  // 192*192
      case 6:        temp = (const float*)d_in[i]; break;   // heads
    }
  }
  k1_qkv_dw<<<dim3(4096, 3), 256>>>(x, qkvw, dww);
  k2_attn<<<dim3(4096, 6), 256>>>(temp);
  k3_proj<<<4096, 256>>>(projw, (float*)d_out);
}